// round 12
// baseline (speedup 1.0000x reference)
#include <cuda_runtime.h>
#include <cuda_fp16.h>
#include <mma.h>
#include <cstdint>

using namespace nvcuda;

// Problem constants (fixed shapes)
#define N_NODES 50000
#define N_EDGES 1600000
constexpr int NPAD = 50048;              // padded to 64-row multiple for wmma

constexpr int SCAN_BS = 512;
constexpr int SCAN_NB = (N_NODES + SCAN_BS - 1) / SCAN_BS;  // 98

// ---------------------------------------------------------------------------
// Scratch
// ---------------------------------------------------------------------------
__device__ float g_deg[N_NODES];
__device__ float g_dis[N_NODES];
__device__ float g_diag[N_NODES];
__device__ int   g_cnt[N_NODES];
__device__ int   g_rowptr[N_NODES + 1];
__device__ int   g_cursor[N_NODES];
__device__ int2  g_cw[N_EDGES];          // packed (col, w-bits)
__device__ int   g_bsum[SCAN_NB];
__device__ int   g_boff[SCAN_NB];
// Clenshaw buffers (fp32, row-padded to NPAD):
__device__ float g_U[(size_t)NPAD * 256];
__device__ float g_H[(size_t)NPAD * 64];
__device__ float g_V[(size_t)NPAD * 160];
// fp16 H (GEMM2 input, produced by spmm3 epilogue; pad rows zeroed)
__device__ __half g_Hh[(size_t)NPAD * 64];
// fp16 gather mirrors (ping-pong), stride = FEATS (64 or 40)
__device__ __half g_F16a[(size_t)N_NODES * 64];
__device__ __half g_F16b[(size_t)N_NODES * 64];

// ---------------------------------------------------------------------------
// Preprocessing
// ---------------------------------------------------------------------------
__global__ void k_zero_nodes() {
    int i = blockIdx.x * blockDim.x + threadIdx.x;
    if (i < N_NODES) { g_deg[i] = 0.f; g_cnt[i] = 0; }
}

__global__ void k_degree(const int* __restrict__ src, const int* __restrict__ dst,
                         const float* __restrict__ ew) {
    int e = blockIdx.x * blockDim.x + threadIdx.x;
    if (e < N_EDGES) {
        atomicAdd(&g_deg[src[e]], ew[e]);
        atomicAdd(&g_cnt[dst[e]], 1);
    }
}

// ---- scan phase 1 (per-block sums), fused with degree normalization ----
__global__ void k_scan1() {
    __shared__ int ws[SCAN_BS / 32];
    const int tid = threadIdx.x;
    const int i = blockIdx.x * SCAN_BS + tid;
    int v = 0;
    if (i < N_NODES) {
        v = g_cnt[i];
        float d = g_deg[i];
        g_dis[i]  = (d > 0.f) ? rsqrtf(fmaxf(d, 1e-12f)) : 0.f;
        g_diag[i] = (d > 0.f) ? 0.f : -1.f;
    }
    int s = v;
#pragma unroll
    for (int off = 16; off > 0; off >>= 1)
        s += __shfl_down_sync(0xffffffffu, s, off);
    if ((tid & 31) == 0) ws[tid >> 5] = s;
    __syncthreads();
    if (tid < SCAN_BS / 32) {
        int t = ws[tid];
#pragma unroll
        for (int off = SCAN_BS / 64; off > 0; off >>= 1)
            t += __shfl_down_sync(0xffffffffu, t, off);
        if (tid == 0) g_bsum[blockIdx.x] = t;
    }
}

__global__ void k_scan2() {
    __shared__ int sm[128];
    const int tid = threadIdx.x;
    int v = (tid < SCAN_NB) ? g_bsum[tid] : 0;
    sm[tid] = v;
    __syncthreads();
#pragma unroll
    for (int off = 1; off < 128; off <<= 1) {
        int y = (tid >= off) ? sm[tid - off] : 0;
        __syncthreads();
        sm[tid] += y;
        __syncthreads();
    }
    if (tid < SCAN_NB) g_boff[tid] = sm[tid] - v;
    if (tid == 127) g_rowptr[N_NODES] = sm[127];
}

__global__ void k_scan3() {
    __shared__ int ws[SCAN_BS / 32];
    const int tid = threadIdx.x;
    const int lane = tid & 31;
    const int wid = tid >> 5;
    const int i = blockIdx.x * SCAN_BS + tid;
    int v = (i < N_NODES) ? g_cnt[i] : 0;
    int x = v;
#pragma unroll
    for (int off = 1; off < 32; off <<= 1) {
        int y = __shfl_up_sync(0xffffffffu, x, off);
        if (lane >= off) x += y;
    }
    if (lane == 31) ws[wid] = x;
    __syncthreads();
    if (wid == 0) {
        int s = (lane < SCAN_BS / 32) ? ws[lane] : 0;
#pragma unroll
        for (int off = 1; off < SCAN_BS / 32; off <<= 1) {
            int y = __shfl_up_sync(0xffffffffu, s, off);
            if (lane >= off) s += y;
        }
        if (lane < SCAN_BS / 32) ws[lane] = s;
    }
    __syncthreads();
    int excl = x - v + ((wid > 0) ? ws[wid - 1] : 0) + g_boff[blockIdx.x];
    if (i < N_NODES) { g_rowptr[i] = excl; g_cursor[i] = excl; }
}

__global__ void k_fill(const int* __restrict__ src, const int* __restrict__ dst,
                       const float* __restrict__ ew) {
    int e = blockIdx.x * blockDim.x + threadIdx.x;
    if (e < N_EDGES) {
        int s = src[e], d = dst[e];
        int pos = atomicAdd(&g_cursor[d], 1);
        float w = -g_dis[s] * ew[e] * g_dis[d];
        g_cw[pos] = make_int2(s, __float_as_int(w));
    }
}

// ---------------------------------------------------------------------------
// helpers
// ---------------------------------------------------------------------------
__device__ __forceinline__ uint4 pack8(const float4 f0, const float4 f1) {
    __half2 h0 = __float22half2_rn(make_float2(f0.x, f0.y));
    __half2 h1 = __float22half2_rn(make_float2(f0.z, f0.w));
    __half2 h2 = __float22half2_rn(make_float2(f1.x, f1.y));
    __half2 h3 = __float22half2_rn(make_float2(f1.z, f1.w));
    uint4 pk;
    pk.x = *reinterpret_cast<unsigned*>(&h0);
    pk.y = *reinterpret_cast<unsigned*>(&h1);
    pk.z = *reinterpret_cast<unsigned*>(&h2);
    pk.w = *reinterpret_cast<unsigned*>(&h3);
    return pk;
}

// zero pad rows of g_Hh (rows N_NODES .. NPAD)
__global__ void k_pad_hh() {
    const int t = blockIdx.x * blockDim.x + threadIdx.x;
    const int total = (NPAD - N_NODES) * 64;
    if (t < total) g_Hh[(size_t)N_NODES * 64 + t] = __float2half_rn(0.f);
}

// fp32 slice -> fp16 mirror (row stride ss -> dense FEATS)
template <int FEATS>
__global__ void k_mirror(const float* __restrict__ src, int ss,
                         __half* __restrict__ dst) {
    constexpr int GPR = FEATS / 8;    // uint4 groups per row
    const int i = blockIdx.x * blockDim.x + threadIdx.x;
    if (i >= N_NODES * GPR) return;
    const int row = i / GPR;
    const int g = i - row * GPR;
    const float4 f0 = *(const float4*)(src + (size_t)row * ss + g * 8);
    const float4 f1 = *(const float4*)(src + (size_t)row * ss + g * 8 + 4);
    *(uint4*)(dst + (size_t)row * FEATS + g * 8) = pack8(f0, f1);
}

// ---------------------------------------------------------------------------
// Clenshaw SpMM step: out = alpha * (L_hat @ in16) + u [- v] [+ bias] [relu]
// Gathered operand fp16; accumulation + row-local fp32. Gather LDGs are
// PREDICATED on (j+t) < deg so tail iterations of the warp-max loop cost no
// bandwidth (only the 8B cw load + zero-FMAs).
// ---------------------------------------------------------------------------
template <int FEATS, bool HASV, bool HASBIAS, bool RELU>
__global__ __launch_bounds__(256) void k_spmm(
        const __half* __restrict__ in16,
        const float* __restrict__ u, int su,
        const float* __restrict__ v, int sv,
        float alpha,
        float* __restrict__ out, int so,
        __half* __restrict__ out16,
        const float* __restrict__ bias) {
    constexpr int LPR = FEATS / 8;   // lanes per row
    constexpr int RPW = 32 / LPR;    // rows per warp

    const int gw = (blockIdx.x * blockDim.x + threadIdx.x) >> 5;
    const int lane = threadIdx.x & 31;
    const int row_base = gw * RPW;
    if (row_base >= N_NODES) return;

    const int sub = lane / LPR;
    const int li = lane % LPR;
    const bool act = (sub < RPW) && (row_base + sub < N_NODES);
    const int row = act ? (row_base + sub) : 0;

    int beg = 0, deg = 0;
    if (act) {
        beg = __ldg(&g_rowptr[row]);
        deg = __ldg(&g_rowptr[row + 1]) - beg;
    }
    const int m = __reduce_max_sync(0xffffffffu, deg);
    const int lv = li * 8;

    float a[8];
#pragma unroll
    for (int i = 0; i < 8; i++) a[i] = 0.f;

    for (int j = 0; j < m; j += 4) {
        int cc[4];
        float wt[4];
#pragma unroll
        for (int t = 0; t < 4; t++) {
            int2 cwp = make_int2(0, 0);
            if ((j + t) < deg) cwp = __ldg(&g_cw[beg + j + t]);
            cc[t] = cwp.x;
            wt[t] = __int_as_float(cwp.y);
        }
        uint4 gv[4];
#pragma unroll
        for (int t = 0; t < 4; t++) {
            gv[t] = make_uint4(0u, 0u, 0u, 0u);
            if ((j + t) < deg)
                gv[t] = *(const uint4*)(in16 + (size_t)cc[t] * FEATS + lv);
        }
#pragma unroll
        for (int t = 0; t < 4; t++) {
            const __half2* hp = reinterpret_cast<const __half2*>(&gv[t]);
            const float2 f0 = __half22float2(hp[0]);
            const float2 f1 = __half22float2(hp[1]);
            const float2 f2 = __half22float2(hp[2]);
            const float2 f3 = __half22float2(hp[3]);
            a[0] = fmaf(wt[t], f0.x, a[0]); a[1] = fmaf(wt[t], f0.y, a[1]);
            a[2] = fmaf(wt[t], f1.x, a[2]); a[3] = fmaf(wt[t], f1.y, a[3]);
            a[4] = fmaf(wt[t], f2.x, a[4]); a[5] = fmaf(wt[t], f2.y, a[5]);
            a[6] = fmaf(wt[t], f3.x, a[6]); a[7] = fmaf(wt[t], f3.y, a[7]);
        }
    }

    if (!act) return;

    // diagonal term
    {
        const float dg = g_diag[row];
        const uint4 gv = *(const uint4*)(in16 + (size_t)row * FEATS + lv);
        const __half2* hp = reinterpret_cast<const __half2*>(&gv);
        const float2 f0 = __half22float2(hp[0]);
        const float2 f1 = __half22float2(hp[1]);
        const float2 f2 = __half22float2(hp[2]);
        const float2 f3 = __half22float2(hp[3]);
        a[0] = fmaf(dg, f0.x, a[0]); a[1] = fmaf(dg, f0.y, a[1]);
        a[2] = fmaf(dg, f1.x, a[2]); a[3] = fmaf(dg, f1.y, a[3]);
        a[4] = fmaf(dg, f2.x, a[4]); a[5] = fmaf(dg, f2.y, a[5]);
        a[6] = fmaf(dg, f3.x, a[6]); a[7] = fmaf(dg, f3.y, a[7]);
    }

    float r[8];
    {
        const float4 u0 = *(const float4*)(u + (size_t)row * su + lv);
        const float4 u1 = *(const float4*)(u + (size_t)row * su + lv + 4);
        r[0] = fmaf(alpha, a[0], u0.x); r[1] = fmaf(alpha, a[1], u0.y);
        r[2] = fmaf(alpha, a[2], u0.z); r[3] = fmaf(alpha, a[3], u0.w);
        r[4] = fmaf(alpha, a[4], u1.x); r[5] = fmaf(alpha, a[5], u1.y);
        r[6] = fmaf(alpha, a[6], u1.z); r[7] = fmaf(alpha, a[7], u1.w);
    }
    if constexpr (HASV) {
        const float4 v0 = *(const float4*)(v + (size_t)row * sv + lv);
        const float4 v1 = *(const float4*)(v + (size_t)row * sv + lv + 4);
        r[0] -= v0.x; r[1] -= v0.y; r[2] -= v0.z; r[3] -= v0.w;
        r[4] -= v1.x; r[5] -= v1.y; r[6] -= v1.z; r[7] -= v1.w;
    }
    if constexpr (HASBIAS) {
        const float4 b0 = *(const float4*)(bias + lv);
        const float4 b1 = *(const float4*)(bias + lv + 4);
        r[0] += b0.x; r[1] += b0.y; r[2] += b0.z; r[3] += b0.w;
        r[4] += b1.x; r[5] += b1.y; r[6] += b1.z; r[7] += b1.w;
    }
    if constexpr (RELU) {
#pragma unroll
        for (int i = 0; i < 8; i++) r[i] = fmaxf(r[i], 0.f);
    }

    *(float4*)(out + (size_t)row * so + lv) = make_float4(r[0], r[1], r[2], r[3]);
    *(float4*)(out + (size_t)row * so + lv + 4) = make_float4(r[4], r[5], r[6], r[7]);

    if (out16 != nullptr) {
        *(uint4*)(out16 + (size_t)row * FEATS + lv) =
            pack8(make_float4(r[0], r[1], r[2], r[3]),
                  make_float4(r[4], r[5], r[6], r[7]));
    }
}

// ---------------------------------------------------------------------------
// fp16 tensor-core GEMM (wmma): out[NPAD x MTOT] = A @ remap(W)
// A is fp32 (A32=true: converted during SMEM staging, lda cols, rows >= N
// zero-padded) or fp16 dense KD (A32=false). W is fp32, slice-remapped +
// converted during the B staging. CTA: 256 thr = 8 warps (4 row x 2 col
// groups), BM=64 rows, BN cols. HALVES: column split via even/odd CTA.
// ---------------------------------------------------------------------------
template <int KD, int MTOT, int BN, int SW, int HALVES, bool A32>
__global__ __launch_bounds__(256) void k_gemm16(
        const void* __restrict__ Aptr, int lda,
        const float* __restrict__ W,
        float* __restrict__ out, int ldo) {
    constexpr int BM = 64;
    constexpr int WCOL = BN / 2;          // cols per warp group
    constexpr int NFRAG = WCOL / 16;      // fragments per warp
    extern __shared__ char shraw[];
    __half* Bs = reinterpret_cast<__half*>(shraw);   // KD x BN
    __half* As = Bs + KD * BN;                        // BM x KD

    const int tid = threadIdx.x;
    const int wid = tid >> 5;
    const int half_id = (HALVES == 2) ? (blockIdx.x & 1) : 0;
    const int c0 = half_id * BN;
    const int bstart = (HALVES == 2) ? (blockIdx.x >> 1) : blockIdx.x;
    const int bstride = (HALVES == 2) ? (gridDim.x >> 1) : gridDim.x;

    // stage B (KD x BN) from fp32 W with slice remap + fp16 convert
    for (int t = tid; t < KD * BN; t += 256) {
        const int kd = t / BN;
        const int c = t - kd * BN;
        const int cg = c0 + c;
        const int s = cg / SW;
        const int j = cg - s * SW;
        Bs[(size_t)kd * BN + c] =
            __float2half_rn(W[((size_t)(s * KD + kd)) * SW + j]);
    }
    __syncthreads();

    const int wr = wid >> 1;      // 0..3
    const int wc = wid & 1;       // 0..1
    const int ntiles = NPAD / BM;

    for (int tile = bstart; tile < ntiles; tile += bstride) {
        const int row0 = tile * BM;
        // stage A tile (BM x KD) as fp16
        if constexpr (A32) {
            const float* Af = (const float*)Aptr;
            for (int t = tid; t < BM * KD / 8; t += 256) {
                const int idx = t * 8;
                const int r = idx / KD;
                const int k = idx - r * KD;
                const int row = row0 + r;
                uint4 pk = make_uint4(0u, 0u, 0u, 0u);
                if (row < N_NODES) {
                    const float4 f0 = *(const float4*)(Af + (size_t)row * lda + k);
                    const float4 f1 = *(const float4*)(Af + (size_t)row * lda + k + 4);
                    pk = pack8(f0, f1);
                }
                *(uint4*)(As + (size_t)r * KD + k) = pk;
            }
        } else {
            const __half* Ah = (const __half*)Aptr;
            for (int t = tid; t < BM * KD / 8; t += 256) {
                const int idx = t * 8;
                const int r = idx / KD;
                const int k = idx - r * KD;
                *(uint4*)(As + (size_t)r * KD + k) =
                    *(const uint4*)(Ah + (size_t)(row0 + r) * KD + k);
            }
        }
        __syncthreads();

        wmma::fragment<wmma::accumulator, 16, 16, 16, float> acc[NFRAG];
#pragma unroll
        for (int f = 0; f < NFRAG; f++) wmma::fill_fragment(acc[f], 0.f);

#pragma unroll
        for (int k0 = 0; k0 < KD; k0 += 16) {
            wmma::fragment<wmma::matrix_a, 16, 16, 16, __half, wmma::row_major> af;
            wmma::load_matrix_sync(af, As + (size_t)(wr * 16) * KD + k0, KD);
#pragma unroll
            for (int f = 0; f < NFRAG; f++) {
                wmma::fragment<wmma::matrix_b, 16, 16, 16, __half, wmma::row_major> bf;
                wmma::load_matrix_sync(bf, Bs + (size_t)k0 * BN + wc * WCOL + f * 16, BN);
                wmma::mma_sync(acc[f], af, bf, acc[f]);
            }
        }

#pragma unroll
        for (int f = 0; f < NFRAG; f++) {
            wmma::store_matrix_sync(
                out + (size_t)(row0 + wr * 16) * ldo + c0 + wc * WCOL + f * 16,
                acc[f], ldo, wmma::mem_row_major);
        }
        __syncthreads();
    }
}

// ---------------------------------------------------------------------------
// Launch
// ---------------------------------------------------------------------------
extern "C" void kernel_launch(void* const* d_in, const int* in_sizes, int n_in,
                              void* d_out, int out_size) {
    const float* x  = (const float*)d_in[0];
    const int*   ei = (const int*)d_in[1];
    const float* ew = (const float*)d_in[2];
    const float* W1 = (const float*)d_in[3];
    const float* b1 = (const float*)d_in[4];
    const float* W2 = (const float*)d_in[5];
    const float* b2 = (const float*)d_in[6];
    const int* src = ei;
    const int* dst = ei + N_EDGES;

    float *U, *H, *V;
    __half *bufA, *bufB, *Hh;
    cudaGetSymbolAddress((void**)&U, g_U);
    cudaGetSymbolAddress((void**)&H, g_H);
    cudaGetSymbolAddress((void**)&V, g_V);
    cudaGetSymbolAddress((void**)&bufA, g_F16a);
    cudaGetSymbolAddress((void**)&bufB, g_F16b);
    cudaGetSymbolAddress((void**)&Hh, g_Hh);

    // smem: G1 Bs 128x128 + As 64x128 fp16 = 48KB; G2 Bs 64x160 + As 64x64 = 28KB
    const int smem1 = (128 * 128 + 64 * 128) * 2;
    const int smem2 = (64 * 160 + 64 * 64) * 2;
    cudaFuncSetAttribute((const void*)k_gemm16<128, 256, 128, 64, 2, true>,
                         cudaFuncAttributeMaxDynamicSharedMemorySize, smem1);
    cudaFuncSetAttribute((const void*)k_gemm16<64, 160, 160, 40, 1, false>,
                         cudaFuncAttributeMaxDynamicSharedMemorySize, smem2);

    const int ngrid = (N_NODES + 255) / 256;
    const int egrid = (N_EDGES + 255) / 256;
    const int warps64 = (N_NODES + 3) / 4;           // RPW=4
    const int sgrid64 = (warps64 + 7) / 8;
    const int warps40 = (N_NODES + 5) / 6;           // RPW=6
    const int sgrid40 = (warps40 + 7) / 8;

    static cudaStream_t s2 = nullptr;
    static cudaEvent_t evFork = nullptr, evJoin = nullptr;
    if (s2 == nullptr) {
        cudaStreamCreateWithFlags(&s2, cudaStreamNonBlocking);
        cudaEventCreateWithFlags(&evFork, cudaEventDisableTiming);
        cudaEventCreateWithFlags(&evJoin, cudaEventDisableTiming);
    }

    // --- Fork: preprocessing + Hh pad on s2; GEMM1 path on main ---
    cudaEventRecord(evFork, 0);
    cudaStreamWaitEvent(s2, evFork, 0);

    k_zero_nodes<<<ngrid, 256, 0, s2>>>();
    k_degree<<<egrid, 256, 0, s2>>>(src, dst, ew);
    k_scan1<<<SCAN_NB, SCAN_BS, 0, s2>>>();
    k_scan2<<<1, 128, 0, s2>>>();
    k_scan3<<<SCAN_NB, SCAN_BS, 0, s2>>>();
    k_fill<<<egrid, 256, 0, s2>>>(src, dst, ew);
    k_pad_hh<<<((NPAD - N_NODES) * 64 + 255) / 256, 256, 0, s2>>>();
    cudaEventRecord(evJoin, s2);

    // main: tensor-core GEMM1 (conversion fused into staging), U3 mirror
    k_gemm16<128, 256, 128, 64, 2, true><<<592, 256, smem1>>>(
        x, 128, W1, U, 256);
    k_mirror<64><<<(N_NODES * 8 + 255) / 256, 256>>>(U + 192, 256, bufA);

    cudaStreamWaitEvent(0, evJoin, 0);   // join before first SpMM

    float* U0 = U;
    float* U1 = U + 64;
    float* U2 = U + 128;
    // ---- Layer 1 (Clenshaw at F=64) ----
    // b2c = 2*L@U3 + U2    (overwrites U2; fp16 mirror -> bufB)
    k_spmm<64, false, false, false><<<sgrid64, 256>>>(
        bufA, U2, 256, nullptr, 0, 2.f, U2, 256, bufB, nullptr);
    // b1c = 2*L@b2c + U1 - U3   (overwrites U1; fp16 mirror -> bufA)
    k_spmm<64, true, false, false><<<sgrid64, 256>>>(
        bufB, U1, 256, U + 192, 256, 2.f, U1, 256, bufA, nullptr);
    // H = relu(L@b1c + U0 - b2c + bias1)  (fp16 mirror -> Hh for GEMM2)
    k_spmm<64, true, true, true><<<sgrid64, 256>>>(
        bufA, U0, 256, U2, 256, 1.f, H, 64, Hh, b1);

    // ---- Layer 2 (Clenshaw at F=40) ----
    // V = Hh @ remap(W2)  (tensor-core), V3 mirror -> bufA
    k_gemm16<64, 160, 160, 40, 1, false><<<782, 256, smem2>>>(
        Hh, 64, W2, V, 160);
    k_mirror<40><<<(N_NODES * 5 + 255) / 256, 256>>>(V + 120, 160, bufA);

    float* V0 = V;
    float* V1 = V + 40;
    float* V2 = V + 80;
    // c2 = 2*L@V3 + V2    (overwrites V2; fp16 mirror -> bufB)
    k_spmm<40, false, false, false><<<sgrid40, 256>>>(
        bufA, V2, 160, nullptr, 0, 2.f, V2, 160, bufB, nullptr);
    // c1 = 2*L@c2 + V1 - V3   (overwrites V1; fp16 mirror -> bufA)
    k_spmm<40, true, false, false><<<sgrid40, 256>>>(
        bufB, V1, 160, V + 120, 160, 2.f, V1, 160, bufA, nullptr);
    // out = L@c1 + V0 - c2 + bias2
    k_spmm<40, true, true, false><<<sgrid40, 256>>>(
        bufA, V0, 160, V2, 160, 1.f, (float*)d_out, 40, nullptr, b2);
}

// round 14
// speedup vs baseline: 1.0258x; 1.0258x over previous
#include <cuda_runtime.h>
#include <cuda_fp16.h>
#include <mma.h>
#include <cstdint>

using namespace nvcuda;

// Problem constants (fixed shapes)
#define N_NODES 50000
#define N_EDGES 1600000
constexpr int NPAD = 50048;              // padded to 64-row multiple for wmma

constexpr int SCAN_BS = 512;
constexpr int SCAN_NB = (N_NODES + SCAN_BS - 1) / SCAN_BS;  // 98

// ---------------------------------------------------------------------------
// Scratch  (g_deg / g_cnt are zero at load time and re-zeroed at the END of
// every launch, so each run starts with them clean without an entry node)
// ---------------------------------------------------------------------------
__device__ float g_deg[N_NODES];
__device__ float g_dis[N_NODES];
__device__ float g_diag[N_NODES];
__device__ int   g_cnt[N_NODES];
__device__ int   g_rowptr[N_NODES + 1];
__device__ int   g_cursor[N_NODES];
__device__ int2  g_cw[N_EDGES];          // packed (col, w-bits)
__device__ int   g_bsum[SCAN_NB];
// Clenshaw buffers (fp32, row-padded to NPAD):
__device__ float g_U[(size_t)NPAD * 256];
__device__ float g_H[(size_t)NPAD * 64];
__device__ float g_V[(size_t)NPAD * 160];
// fp16 H (GEMM2 input; pad rows stay zero from static init — never written)
__device__ __half g_Hh[(size_t)NPAD * 64];
// fp16 gather mirrors (ping-pong), stride = FEATS (64 or 40)
__device__ __half g_F16a[(size_t)N_NODES * 64];
__device__ __half g_F16b[(size_t)N_NODES * 64];

// ---------------------------------------------------------------------------
// Preprocessing
// ---------------------------------------------------------------------------
__global__ void k_zero_nodes() {   // runs at END of pipeline (restores invariant)
    int i = blockIdx.x * blockDim.x + threadIdx.x;
    if (i < N_NODES) { g_deg[i] = 0.f; g_cnt[i] = 0; }
}

__global__ void k_degree(const int* __restrict__ src, const int* __restrict__ dst,
                         const float* __restrict__ ew) {
    int e = blockIdx.x * blockDim.x + threadIdx.x;
    if (e < N_EDGES) {
        atomicAdd(&g_deg[src[e]], ew[e]);
        atomicAdd(&g_cnt[dst[e]], 1);
    }
}

// ---- scan phase 1 (per-block sums), fused with degree normalization ----
__global__ void k_scan1() {
    __shared__ int ws[SCAN_BS / 32];
    const int tid = threadIdx.x;
    const int i = blockIdx.x * SCAN_BS + tid;
    int v = 0;
    if (i < N_NODES) {
        v = g_cnt[i];
        float d = g_deg[i];
        g_dis[i]  = (d > 0.f) ? rsqrtf(fmaxf(d, 1e-12f)) : 0.f;
        g_diag[i] = (d > 0.f) ? 0.f : -1.f;
    }
    int s = v;
#pragma unroll
    for (int off = 16; off > 0; off >>= 1)
        s += __shfl_down_sync(0xffffffffu, s, off);
    if ((tid & 31) == 0) ws[tid >> 5] = s;
    __syncthreads();
    if (tid < SCAN_BS / 32) {
        int t = ws[tid];
#pragma unroll
        for (int off = SCAN_BS / 64; off > 0; off >>= 1)
            t += __shfl_down_sync(0xffffffffu, t, off);
        if (tid == 0) g_bsum[blockIdx.x] = t;
    }
}

// ---- scan phase 2 (fused): block offset recomputed from g_bsum in-block ----
__global__ void k_scan3f() {
    __shared__ int ws[SCAN_BS / 32];
    __shared__ int s_off;
    const int tid = threadIdx.x;
    const int lane = tid & 31;
    const int wid = tid >> 5;
    const int i = blockIdx.x * SCAN_BS + tid;
    int v = (i < N_NODES) ? g_cnt[i] : 0;
    int x = v;
#pragma unroll
    for (int off = 1; off < 32; off <<= 1) {
        int y = __shfl_up_sync(0xffffffffu, x, off);
        if (lane >= off) x += y;
    }
    if (lane == 31) ws[wid] = x;
    __syncthreads();
    if (wid == 0) {
        int s = (lane < SCAN_BS / 32) ? ws[lane] : 0;
#pragma unroll
        for (int off = 1; off < SCAN_BS / 32; off <<= 1) {
            int y = __shfl_up_sync(0xffffffffu, s, off);
            if (lane >= off) s += y;
        }
        if (lane < SCAN_BS / 32) ws[lane] = s;
        // block offset (and grand total on block 0) from the 98 partials
        int accPre = 0, accAll = 0;
        for (int b = lane; b < SCAN_NB; b += 32) {
            const int val = g_bsum[b];
            accAll += val;
            if (b < blockIdx.x) accPre += val;
        }
#pragma unroll
        for (int off = 16; off > 0; off >>= 1) {
            accPre += __shfl_down_sync(0xffffffffu, accPre, off);
            accAll += __shfl_down_sync(0xffffffffu, accAll, off);
        }
        if (lane == 0) {
            s_off = accPre;
            if (blockIdx.x == 0) g_rowptr[N_NODES] = accAll;
        }
    }
    __syncthreads();
    const int excl = x - v + ((wid > 0) ? ws[wid - 1] : 0) + s_off;
    if (i < N_NODES) { g_rowptr[i] = excl; g_cursor[i] = excl; }
}

__global__ void k_fill(const int* __restrict__ src, const int* __restrict__ dst,
                       const float* __restrict__ ew) {
    int e = blockIdx.x * blockDim.x + threadIdx.x;
    if (e < N_EDGES) {
        int s = src[e], d = dst[e];
        int pos = atomicAdd(&g_cursor[d], 1);
        float w = -g_dis[s] * ew[e] * g_dis[d];
        g_cw[pos] = make_int2(s, __float_as_int(w));
    }
}

// ---------------------------------------------------------------------------
// helpers
// ---------------------------------------------------------------------------
__device__ __forceinline__ uint4 pack8(const float4 f0, const float4 f1) {
    __half2 h0 = __float22half2_rn(make_float2(f0.x, f0.y));
    __half2 h1 = __float22half2_rn(make_float2(f0.z, f0.w));
    __half2 h2 = __float22half2_rn(make_float2(f1.x, f1.y));
    __half2 h3 = __float22half2_rn(make_float2(f1.z, f1.w));
    uint4 pk;
    pk.x = *reinterpret_cast<unsigned*>(&h0);
    pk.y = *reinterpret_cast<unsigned*>(&h1);
    pk.z = *reinterpret_cast<unsigned*>(&h2);
    pk.w = *reinterpret_cast<unsigned*>(&h3);
    return pk;
}

// ---------------------------------------------------------------------------
// Clenshaw SpMM step: out = alpha * (L_hat @ in16) + u [- v] [+ bias] [relu]
// Gathered operand fp16; accumulation + row-local fp32.
// ---------------------------------------------------------------------------
template <int FEATS, bool HASV, bool HASBIAS, bool RELU>
__global__ __launch_bounds__(256) void k_spmm(
        const __half* __restrict__ in16,
        const float* __restrict__ u, int su,
        const float* __restrict__ v, int sv,
        float alpha,
        float* __restrict__ out, int so,
        __half* __restrict__ out16,
        const float* __restrict__ bias) {
    constexpr int LPR = FEATS / 8;   // lanes per row
    constexpr int RPW = 32 / LPR;    // rows per warp

    const int gw = (blockIdx.x * blockDim.x + threadIdx.x) >> 5;
    const int lane = threadIdx.x & 31;
    const int row_base = gw * RPW;
    if (row_base >= N_NODES) return;

    const int sub = lane / LPR;
    const int li = lane % LPR;
    const bool act = (sub < RPW) && (row_base + sub < N_NODES);
    const int row = act ? (row_base + sub) : 0;

    int beg = 0, deg = 0;
    if (act) {
        beg = __ldg(&g_rowptr[row]);
        deg = __ldg(&g_rowptr[row + 1]) - beg;
    }
    const int m = __reduce_max_sync(0xffffffffu, deg);
    const int lv = li * 8;

    float a[8];
#pragma unroll
    for (int i = 0; i < 8; i++) a[i] = 0.f;

    for (int j = 0; j < m; j += 4) {
        int cc[4];
        float wt[4];
#pragma unroll
        for (int t = 0; t < 4; t++) {
            int2 cwp = make_int2(0, 0);
            if ((j + t) < deg) cwp = __ldg(&g_cw[beg + j + t]);
            cc[t] = cwp.x;
            wt[t] = __int_as_float(cwp.y);
        }
        uint4 gv[4];
#pragma unroll
        for (int t = 0; t < 4; t++)
            gv[t] = *(const uint4*)(in16 + (size_t)cc[t] * FEATS + lv);
#pragma unroll
        for (int t = 0; t < 4; t++) {
            const __half2* hp = reinterpret_cast<const __half2*>(&gv[t]);
            const float2 f0 = __half22float2(hp[0]);
            const float2 f1 = __half22float2(hp[1]);
            const float2 f2 = __half22float2(hp[2]);
            const float2 f3 = __half22float2(hp[3]);
            a[0] = fmaf(wt[t], f0.x, a[0]); a[1] = fmaf(wt[t], f0.y, a[1]);
            a[2] = fmaf(wt[t], f1.x, a[2]); a[3] = fmaf(wt[t], f1.y, a[3]);
            a[4] = fmaf(wt[t], f2.x, a[4]); a[5] = fmaf(wt[t], f2.y, a[5]);
            a[6] = fmaf(wt[t], f3.x, a[6]); a[7] = fmaf(wt[t], f3.y, a[7]);
        }
    }

    if (!act) return;

    // diagonal term
    {
        const float dg = g_diag[row];
        const uint4 gv = *(const uint4*)(in16 + (size_t)row * FEATS + lv);
        const __half2* hp = reinterpret_cast<const __half2*>(&gv);
        const float2 f0 = __half22float2(hp[0]);
        const float2 f1 = __half22float2(hp[1]);
        const float2 f2 = __half22float2(hp[2]);
        const float2 f3 = __half22float2(hp[3]);
        a[0] = fmaf(dg, f0.x, a[0]); a[1] = fmaf(dg, f0.y, a[1]);
        a[2] = fmaf(dg, f1.x, a[2]); a[3] = fmaf(dg, f1.y, a[3]);
        a[4] = fmaf(dg, f2.x, a[4]); a[5] = fmaf(dg, f2.y, a[5]);
        a[6] = fmaf(dg, f3.x, a[6]); a[7] = fmaf(dg, f3.y, a[7]);
    }

    float r[8];
    {
        const float4 u0 = *(const float4*)(u + (size_t)row * su + lv);
        const float4 u1 = *(const float4*)(u + (size_t)row * su + lv + 4);
        r[0] = fmaf(alpha, a[0], u0.x); r[1] = fmaf(alpha, a[1], u0.y);
        r[2] = fmaf(alpha, a[2], u0.z); r[3] = fmaf(alpha, a[3], u0.w);
        r[4] = fmaf(alpha, a[4], u1.x); r[5] = fmaf(alpha, a[5], u1.y);
        r[6] = fmaf(alpha, a[6], u1.z); r[7] = fmaf(alpha, a[7], u1.w);
    }
    if constexpr (HASV) {
        const float4 v0 = *(const float4*)(v + (size_t)row * sv + lv);
        const float4 v1 = *(const float4*)(v + (size_t)row * sv + lv + 4);
        r[0] -= v0.x; r[1] -= v0.y; r[2] -= v0.z; r[3] -= v0.w;
        r[4] -= v1.x; r[5] -= v1.y; r[6] -= v1.z; r[7] -= v1.w;
    }
    if constexpr (HASBIAS) {
        const float4 b0 = *(const float4*)(bias + lv);
        const float4 b1 = *(const float4*)(bias + lv + 4);
        r[0] += b0.x; r[1] += b0.y; r[2] += b0.z; r[3] += b0.w;
        r[4] += b1.x; r[5] += b1.y; r[6] += b1.z; r[7] += b1.w;
    }
    if constexpr (RELU) {
#pragma unroll
        for (int i = 0; i < 8; i++) r[i] = fmaxf(r[i], 0.f);
    }

    *(float4*)(out + (size_t)row * so + lv) = make_float4(r[0], r[1], r[2], r[3]);
    *(float4*)(out + (size_t)row * so + lv + 4) = make_float4(r[4], r[5], r[6], r[7]);

    if (out16 != nullptr) {
        *(uint4*)(out16 + (size_t)row * FEATS + lv) =
            pack8(make_float4(r[0], r[1], r[2], r[3]),
                  make_float4(r[4], r[5], r[6], r[7]));
    }
}

// ---------------------------------------------------------------------------
// fp16 tensor-core GEMM (wmma) with fused fp16 mirror of tail columns.
// out[NPAD x MTOT] = A @ remap(W); A fp32 (A32) or fp16 dense; W fp32
// remapped+converted during staging. After storing a tile, the CTA covering
// the tail columns re-reads cols [MIROFF, MTOT) through L1 and writes the
// fp16 mirror (stride MIRW).
// ---------------------------------------------------------------------------
template <int KD, int MTOT, int BN, int SW, int HALVES, bool A32,
          int MIROFF, int MIRW>
__global__ __launch_bounds__(256) void k_gemm16(
        const void* __restrict__ Aptr, int lda,
        const float* __restrict__ W,
        float* __restrict__ out, int ldo,
        __half* __restrict__ mir) {
    constexpr int BM = 64;
    constexpr int WCOL = BN / 2;          // cols per warp group
    constexpr int NFRAG = WCOL / 16;      // fragments per warp
    extern __shared__ char shraw[];
    __half* Bs = reinterpret_cast<__half*>(shraw);   // KD x BN
    __half* As = Bs + KD * BN;                        // BM x KD

    const int tid = threadIdx.x;
    const int wid = tid >> 5;
    const int half_id = (HALVES == 2) ? (blockIdx.x & 1) : 0;
    const int c0 = half_id * BN;
    const int bstart = (HALVES == 2) ? (blockIdx.x >> 1) : blockIdx.x;
    const int bstride = (HALVES == 2) ? (gridDim.x >> 1) : gridDim.x;
    const bool has_tail = (c0 + BN == MTOT);

    // stage B (KD x BN) from fp32 W with slice remap + fp16 convert
    for (int t = tid; t < KD * BN; t += 256) {
        const int kd = t / BN;
        const int c = t - kd * BN;
        const int cg = c0 + c;
        const int s = cg / SW;
        const int j = cg - s * SW;
        Bs[(size_t)kd * BN + c] =
            __float2half_rn(W[((size_t)(s * KD + kd)) * SW + j]);
    }
    __syncthreads();

    const int wr = wid >> 1;      // 0..3
    const int wc = wid & 1;       // 0..1
    const int ntiles = NPAD / BM;

    for (int tile = bstart; tile < ntiles; tile += bstride) {
        const int row0 = tile * BM;
        // stage A tile (BM x KD) as fp16
        if constexpr (A32) {
            const float* Af = (const float*)Aptr;
            for (int t = tid; t < BM * KD / 8; t += 256) {
                const int idx = t * 8;
                const int r = idx / KD;
                const int k = idx - r * KD;
                const int row = row0 + r;
                uint4 pk = make_uint4(0u, 0u, 0u, 0u);
                if (row < N_NODES) {
                    const float4 f0 = *(const float4*)(Af + (size_t)row * lda + k);
                    const float4 f1 = *(const float4*)(Af + (size_t)row * lda + k + 4);
                    pk = pack8(f0, f1);
                }
                *(uint4*)(As + (size_t)r * KD + k) = pk;
            }
        } else {
            const __half* Ah = (const __half*)Aptr;
            for (int t = tid; t < BM * KD / 8; t += 256) {
                const int idx = t * 8;
                const int r = idx / KD;
                const int k = idx - r * KD;
                *(uint4*)(As + (size_t)r * KD + k) =
                    *(const uint4*)(Ah + (size_t)(row0 + r) * KD + k);
            }
        }
        __syncthreads();

        wmma::fragment<wmma::accumulator, 16, 16, 16, float> acc[NFRAG];
#pragma unroll
        for (int f = 0; f < NFRAG; f++) wmma::fill_fragment(acc[f], 0.f);

#pragma unroll
        for (int k0 = 0; k0 < KD; k0 += 16) {
            wmma::fragment<wmma::matrix_a, 16, 16, 16, __half, wmma::row_major> af;
            wmma::load_matrix_sync(af, As + (size_t)(wr * 16) * KD + k0, KD);
#pragma unroll
            for (int f = 0; f < NFRAG; f++) {
                wmma::fragment<wmma::matrix_b, 16, 16, 16, __half, wmma::row_major> bf;
                wmma::load_matrix_sync(bf, Bs + (size_t)k0 * BN + wc * WCOL + f * 16, BN);
                wmma::mma_sync(acc[f], af, bf, acc[f]);
            }
        }

#pragma unroll
        for (int f = 0; f < NFRAG; f++) {
            wmma::store_matrix_sync(
                out + (size_t)(row0 + wr * 16) * ldo + c0 + wc * WCOL + f * 16,
                acc[f], ldo, wmma::mem_row_major);
        }

        // fused fp16 mirror of tail columns (re-read just-stored fp32 via L1)
        if constexpr (MIRW > 0) {
            if (has_tail) {
                __syncthreads();
                constexpr int GROUPS = MIRW / 8;
                for (int t = tid; t < BM * GROUPS; t += 256) {
                    const int r = t / GROUPS;
                    const int g = t - r * GROUPS;
                    const int row = row0 + r;
                    if (row < N_NODES) {
                        const float4 f0 =
                            *(const float4*)(out + (size_t)row * ldo + MIROFF + g * 8);
                        const float4 f1 =
                            *(const float4*)(out + (size_t)row * ldo + MIROFF + g * 8 + 4);
                        *(uint4*)(mir + (size_t)row * MIRW + g * 8) = pack8(f0, f1);
                    }
                }
            }
        }
        __syncthreads();
    }
}

// ---------------------------------------------------------------------------
// Launch
// ---------------------------------------------------------------------------
extern "C" void kernel_launch(void* const* d_in, const int* in_sizes, int n_in,
                              void* d_out, int out_size) {
    const float* x  = (const float*)d_in[0];
    const int*   ei = (const int*)d_in[1];
    const float* ew = (const float*)d_in[2];
    const float* W1 = (const float*)d_in[3];
    const float* b1 = (const float*)d_in[4];
    const float* W2 = (const float*)d_in[5];
    const float* b2 = (const float*)d_in[6];
    const int* src = ei;
    const int* dst = ei + N_EDGES;

    float *U, *H, *V;
    __half *bufA, *bufB, *Hh;
    cudaGetSymbolAddress((void**)&U, g_U);
    cudaGetSymbolAddress((void**)&H, g_H);
    cudaGetSymbolAddress((void**)&V, g_V);
    cudaGetSymbolAddress((void**)&bufA, g_F16a);
    cudaGetSymbolAddress((void**)&bufB, g_F16b);
    cudaGetSymbolAddress((void**)&Hh, g_Hh);

    // smem: G1 Bs 128x128 + As 64x128 fp16 = 48KB; G2 Bs 64x160 + As 64x64 = 28KB
    const int smem1 = (128 * 128 + 64 * 128) * 2;
    const int smem2 = (64 * 160 + 64 * 64) * 2;
    cudaFuncSetAttribute((const void*)k_gemm16<128, 256, 128, 64, 2, true, 192, 64>,
                         cudaFuncAttributeMaxDynamicSharedMemorySize, smem1);
    cudaFuncSetAttribute((const void*)k_gemm16<64, 160, 160, 40, 1, false, 120, 40>,
                         cudaFuncAttributeMaxDynamicSharedMemorySize, smem2);

    const int ngrid = (N_NODES + 255) / 256;
    const int egrid = (N_EDGES + 255) / 256;
    const int warps64 = (N_NODES + 3) / 4;           // RPW=4
    const int sgrid64 = (warps64 + 7) / 8;
    const int warps40 = (N_NODES + 5) / 6;           // RPW=6
    const int sgrid40 = (warps40 + 7) / 8;

    static cudaStream_t s2 = nullptr;
    static cudaEvent_t evFork = nullptr, evJoin = nullptr, evZero = nullptr;
    if (s2 == nullptr) {
        cudaStreamCreateWithFlags(&s2, cudaStreamNonBlocking);
        cudaEventCreateWithFlags(&evFork, cudaEventDisableTiming);
        cudaEventCreateWithFlags(&evJoin, cudaEventDisableTiming);
        cudaEventCreateWithFlags(&evZero, cudaEventDisableTiming);
    }

    // --- Fork: preprocessing on s2 (g_deg/g_cnt already zero on entry);
    //     GEMM1 path on main ---
    cudaEventRecord(evFork, 0);
    cudaStreamWaitEvent(s2, evFork, 0);

    k_degree<<<egrid, 256, 0, s2>>>(src, dst, ew);
    k_scan1<<<SCAN_NB, SCAN_BS, 0, s2>>>();
    k_scan3f<<<SCAN_NB, SCAN_BS, 0, s2>>>();
    k_fill<<<egrid, 256, 0, s2>>>(src, dst, ew);
    cudaEventRecord(evJoin, s2);
    // restore the zero invariant for the next replay (off critical path,
    // runs concurrently with the main SpMM chain; joined at the very end)
    k_zero_nodes<<<ngrid, 256, 0, s2>>>();
    cudaEventRecord(evZero, s2);

    // main: tensor-core GEMM1 (fp16 convert fused in staging; U3 fp16 mirror
    // fused in epilogue -> bufA)
    k_gemm16<128, 256, 128, 64, 2, true, 192, 64><<<592, 256, smem1>>>(
        x, 128, W1, U, 256, bufA);

    cudaStreamWaitEvent(0, evJoin, 0);   // join before first SpMM

    float* U0 = U;
    float* U1 = U + 64;
    float* U2 = U + 128;
    // ---- Layer 1 (Clenshaw at F=64) ----
    // b2c = 2*L@U3 + U2    (overwrites U2; fp16 mirror -> bufB)
    k_spmm<64, false, false, false><<<sgrid64, 256>>>(
        bufA, U2, 256, nullptr, 0, 2.f, U2, 256, bufB, nullptr);
    // b1c = 2*L@b2c + U1 - U3   (overwrites U1; fp16 mirror -> bufA)
    k_spmm<64, true, false, false><<<sgrid64, 256>>>(
        bufB, U1, 256, U + 192, 256, 2.f, U1, 256, bufA, nullptr);
    // H = relu(L@b1c + U0 - b2c + bias1)  (fp16 mirror -> Hh for GEMM2)
    k_spmm<64, true, true, true><<<sgrid64, 256>>>(
        bufA, U0, 256, U2, 256, 1.f, H, 64, Hh, b1);

    // ---- Layer 2 (Clenshaw at F=40) ----
    // V = Hh @ remap(W2)  (tensor-core; V3 fp16 mirror fused -> bufA)
    k_gemm16<64, 160, 160, 40, 1, false, 120, 40><<<782, 256, smem2>>>(
        Hh, 64, W2, V, 160, bufA);

    float* V0 = V;
    float* V1 = V + 40;
    float* V2 = V + 80;
    // c2 = 2*L@V3 + V2    (overwrites V2; fp16 mirror -> bufB)
    k_spmm<40, false, false, false><<<sgrid40, 256>>>(
        bufA, V2, 160, nullptr, 0, 2.f, V2, 160, bufB, nullptr);
    // c1 = 2*L@c2 + V1 - V3   (overwrites V1; fp16 mirror -> bufA)
    k_spmm<40, true, false, false><<<sgrid40, 256>>>(
        bufB, V1, 160, V + 120, 160, 2.f, V1, 160, bufA, nullptr);
    // out = L@c1 + V0 - c2 + bias2
    k_spmm<40, true, true, false><<<sgrid40, 256>>>(
        bufA, V0, 160, V2, 160, 1.f, (float*)d_out, 40, nullptr, b2);

    // join s2's tail (zeroing) so the captured graph has no unjoined work
    cudaStreamWaitEvent(0, evZero, 0);
}